// round 6
// baseline (speedup 1.0000x reference)
#include <cuda_runtime.h>
#include <cuda_bf16.h>
#include <cuda_fp16.h>
#include <math.h>
#include <stdint.h>

// Problem constants (match reference)
#define N_NODES  100000
#define N_EDGES  3200000
#define IN_CH    128
#define HID_CH   128
#define OUT_CH   64
#define N_GRAPHS 128

// ---------------- scratch (device globals; no allocation allowed) ----------------
__device__ float g_dinv[N_NODES];
__device__ int   g_cnt[N_NODES];
__device__ int   g_ptr[N_NODES + 1];
__device__ int   g_cursor[N_NODES];
__device__ int   g_bsum[128];
__device__ int   g_boff[128];
__device__ int2  g_csr[N_EDGES];                 // {src, __float_as_int(raw edge weight)}
__device__ __half g_y16[N_NODES * HID_CH];       // dinv-prescaled GEMM output (gather operand)
__device__ float g_h[N_NODES * HID_CH];          // post-aggregation activations (fp32)
__device__ float g_pool[N_GRAPHS * HID_CH];
__device__ int   g_is64;                         // 1 if index tensors are int64
// bf16-split transposed weights: wt[n*128+k] = W[k*128+n]
__device__ __nv_bfloat16 g_w1hi[HID_CH * IN_CH];
__device__ __nv_bfloat16 g_w1lo[HID_CH * IN_CH];
__device__ __nv_bfloat16 g_w2hi[HID_CH * HID_CH];
__device__ __nv_bfloat16 g_w2lo[HID_CH * HID_CH];

__device__ __forceinline__ uint32_t smem_u32(const void* p) {
    uint32_t a;
    asm("{ .reg .u64 t; cvta.to.shared.u64 t, %1; cvt.u32.u64 %0, t; }" : "=r"(a) : "l"(p));
    return a;
}

// ---------------- index accessor (int32 or int64) ----------------
__device__ __forceinline__ int load_idx(const void* p, long long i, int is64) {
    if (is64) return (int)((const long long*)p)[i];
    return ((const int*)p)[i];
}

// ---------------- init + dtype probe (merged) ----------------
__global__ void k_zero(const int* ei_probe) {
    int i = blockIdx.x * blockDim.x + threadIdx.x;
    if (i == 0) {
        int nz = 0;
        for (int j = 0; j < 64; j++) nz |= ei_probe[2 * j + 1];
        g_is64 = (nz == 0) ? 1 : 0;
    }
    if (i < N_NODES) g_cnt[i] = 0;
    if (i < N_GRAPHS * HID_CH) g_pool[i] = 0.f;
}

// ---------------- weight transpose + bf16 split (both layers, one launch) ----------------
__global__ void k_wsplit(const float* __restrict__ W1, const float* __restrict__ W2) {
    int bid = blockIdx.x;
    const float* W = (bid < 64) ? W1 : W2;
    __nv_bfloat16* hi = (bid < 64) ? g_w1hi : g_w2hi;
    __nv_bfloat16* lo = (bid < 64) ? g_w1lo : g_w2lo;
    int i = (bid & 63) * 256 + threadIdx.x;      // i = k*128 + n
    int k = i >> 7, n = i & 127;
    float w = W[i];
    __nv_bfloat16 h = __float2bfloat16_rn(w);
    __nv_bfloat16 l = __float2bfloat16_rn(w - __bfloat162float(h));
    hi[n * 128 + k] = h;
    lo[n * 128 + k] = l;
}

// ---------------- pass 1: per-target edge counts only ----------------
__global__ void k_pass1(const void* __restrict__ ei) {
    int e = blockIdx.x * blockDim.x + threadIdx.x;
    if (e >= N_EDGES) return;
    int c = load_idx(ei, (long long)N_EDGES + e, g_is64);
    atomicAdd(&g_cnt[c], 1);
}

// ---------------- exclusive scan of counts -> g_ptr ----------------
__global__ void k_scan1(int n) {
    __shared__ int sm[1024];
    int i = blockIdx.x * 1024 + threadIdx.x;
    int v = (i < n) ? g_cnt[i] : 0;
    sm[threadIdx.x] = v;
    __syncthreads();
    for (int off = 1; off < 1024; off <<= 1) {
        int t = (threadIdx.x >= off) ? sm[threadIdx.x - off] : 0;
        __syncthreads();
        sm[threadIdx.x] += t;
        __syncthreads();
    }
    if (i < n) g_ptr[i + 1] = sm[threadIdx.x];
    if (threadIdx.x == 1023) g_bsum[blockIdx.x] = sm[1023];
}

__global__ void k_scan2(int nb) {
    if (threadIdx.x == 0 && blockIdx.x == 0) {
        int acc = 0;
        for (int b = 0; b < nb; b++) { int t = g_bsum[b]; g_boff[b] = acc; acc += t; }
    }
}

// final ptr + cursor init in one pass: cursor[i] = final_ptr[i+1] - cnt[i]
__global__ void k_scan3(int n) {
    int i = blockIdx.x * blockDim.x + threadIdx.x;
    if (i == 0) g_ptr[0] = 0;
    if (i < n) {
        int v = g_ptr[i + 1] + g_boff[i >> 10];
        g_ptr[i + 1] = v;
        g_cursor[i] = v - g_cnt[i];
    }
}

// ---------------- pass 2: fill CSR with (src, raw weight) — no random reads ----------------
__global__ void k_fill(const void* __restrict__ ei, const float* __restrict__ w) {
    int e = blockIdx.x * blockDim.x + threadIdx.x;
    if (e >= N_EDGES) return;
    int is64 = g_is64;
    int r = load_idx(ei, e, is64);
    int c = load_idx(ei, (long long)N_EDGES + e, is64);
    int p = atomicAdd(&g_cursor[c], 1);
    g_csr[p] = make_int2(r, __float_as_int(w[e]));
}

// ---------------- deg from CSR segments + dinv (warp per node, no atomics) ----------------
__global__ void k_degdinv() {
    int node = (blockIdx.x * blockDim.x + threadIdx.x) >> 5;
    if (node >= N_NODES) return;
    int lane = threadIdx.x & 31;
    int beg = g_ptr[node], end = g_ptr[node + 1];
    float s = 0.f;
    for (int e = beg + lane; e < end; e += 32)
        s += __int_as_float(g_csr[e].y);
    #pragma unroll
    for (int o = 16; o > 0; o >>= 1) s += __shfl_xor_sync(0xffffffffu, s, o);
    if (lane == 0) g_dinv[node] = rsqrtf(s + 1.0f);
}

// ---------------- mma.sync GEMM: Y[M,128] = fp16(dinv .* (A[M,128] @ W)) (3x bf16 split) ----------------
// Block = 128 rows x 128 cols, 256 threads (8 warps, 4x2): warp tile 32 rows x 64 cols.
// smem: Ah, Al, Bh, Bl each [128][PADK] bf16 (PADK=136 -> row stride 272B = 68 words == 4 mod 32).
#define PADK 136
#define SME_TOTAL (4 * 128 * PADK * 2)

__global__ __launch_bounds__(256, 1) void k_gemm_tc(const float* __restrict__ A,
                                                    const __nv_bfloat16* __restrict__ wt_hi,
                                                    const __nv_bfloat16* __restrict__ wt_lo,
                                                    __half* __restrict__ Y, int M) {
    extern __shared__ char smem_raw[];
    __nv_bfloat16* Ah = (__nv_bfloat16*)smem_raw;
    __nv_bfloat16* Al = Ah + 128 * PADK;
    __nv_bfloat16* Bh = Al + 128 * PADK;
    __nv_bfloat16* Bl = Bh + 128 * PADK;
    int tid = threadIdx.x;
    int wid = tid >> 5, lane = tid & 31;
    int row0 = blockIdx.x * 128;

    // Load A [128x128 f32] -> hi/lo bf16 split
    for (int g = tid; g < 128 * 32; g += 256) {
        int r = g >> 5, c4 = (g & 31) * 4;
        int gr = row0 + r;
        float4 v = make_float4(0.f, 0.f, 0.f, 0.f);
        if (gr < M) v = ((const float4*)(A + (size_t)gr * 128))[c4 >> 2];
        __nv_bfloat16 h0 = __float2bfloat16_rn(v.x), h1 = __float2bfloat16_rn(v.y);
        __nv_bfloat16 h2 = __float2bfloat16_rn(v.z), h3 = __float2bfloat16_rn(v.w);
        __nv_bfloat16* ah = Ah + r * PADK + c4;
        __nv_bfloat16* al = Al + r * PADK + c4;
        ah[0] = h0; ah[1] = h1; ah[2] = h2; ah[3] = h3;
        al[0] = __float2bfloat16_rn(v.x - __bfloat162float(h0));
        al[1] = __float2bfloat16_rn(v.y - __bfloat162float(h1));
        al[2] = __float2bfloat16_rn(v.z - __bfloat162float(h2));
        al[3] = __float2bfloat16_rn(v.w - __bfloat162float(h3));
    }
    // Load B (pre-split transposed weights): 16-byte vectors
    for (int g = tid; g < 128 * 16; g += 256) {
        int r = g >> 4, c8 = (g & 15) * 8;
        *(float4*)(Bh + r * PADK + c8) = *(const float4*)(wt_hi + r * 128 + c8);
        *(float4*)(Bl + r * PADK + c8) = *(const float4*)(wt_lo + r * 128 + c8);
    }
    __syncthreads();

    int wr = wid & 3;       // row group: rows wr*32 .. wr*32+31
    int wc = wid >> 2;      // col group: cols wc*64 .. wc*64+63
    float acc[2][8][4];
    #pragma unroll
    for (int rt = 0; rt < 2; rt++)
        #pragma unroll
        for (int nt = 0; nt < 8; nt++)
            #pragma unroll
            for (int j = 0; j < 4; j++) acc[rt][nt][j] = 0.f;

    // A frag: row = wr*32 + rt*16 + lane%16, col = (lane/16)*8 (+ kc*16)
    int a_r = wr * 32 + (lane & 15);
    int a_c = (lane >> 4) * 8;
    // B frag: n = wc*64 + nt*8 + lane%8, k = ((lane>>3)&1)*8 (+ kc*16)
    int b_r = wc * 64 + (lane & 7);
    int b_c = ((lane >> 3) & 1) * 8;

    const __nv_bfloat16* Aptr[3] = {Ah, Ah, Al};
    const __nv_bfloat16* Bptr[3] = {Bh, Bl, Bh};

    #pragma unroll
    for (int pass = 0; pass < 3; pass++) {
        uint32_t abase = smem_u32(Aptr[pass] + a_r * PADK + a_c);
        uint32_t bbase = smem_u32(Bptr[pass] + b_r * PADK + b_c);
        #pragma unroll
        for (int kc = 0; kc < 8; kc++) {
            uint32_t a0[2], a1[2], a2[2], a3[2];
            #pragma unroll
            for (int rt = 0; rt < 2; rt++)
                asm volatile("ldmatrix.sync.aligned.m8n8.x4.shared.b16 {%0,%1,%2,%3}, [%4];"
                             : "=r"(a0[rt]), "=r"(a1[rt]), "=r"(a2[rt]), "=r"(a3[rt])
                             : "r"(abase + (uint32_t)(rt * 16 * PADK * 2) + kc * 32));
            #pragma unroll
            for (int nt = 0; nt < 8; nt++) {
                uint32_t b0, b1;
                asm volatile("ldmatrix.sync.aligned.m8n8.x2.shared.b16 {%0,%1}, [%2];"
                             : "=r"(b0), "=r"(b1)
                             : "r"(bbase + (uint32_t)(nt * 8 * PADK * 2) + kc * 32));
                #pragma unroll
                for (int rt = 0; rt < 2; rt++)
                    asm volatile("mma.sync.aligned.m16n8k16.row.col.f32.bf16.bf16.f32 "
                                 "{%0,%1,%2,%3}, {%4,%5,%6,%7}, {%8,%9}, {%0,%1,%2,%3};"
                                 : "+f"(acc[rt][nt][0]), "+f"(acc[rt][nt][1]),
                                   "+f"(acc[rt][nt][2]), "+f"(acc[rt][nt][3])
                                 : "r"(a0[rt]), "r"(a1[rt]), "r"(a2[rt]), "r"(a3[rt]),
                                   "r"(b0), "r"(b1));
            }
        }
    }

    // Epilogue: scale by dinv[row], pack to fp16.
    #pragma unroll
    for (int rt = 0; rt < 2; rt++) {
        int er0 = row0 + wr * 32 + rt * 16 + (lane >> 2);
        int er1 = er0 + 8;
        int ec = wc * 64 + (lane & 3) * 2;
        float d0 = (er0 < M) ? g_dinv[er0] : 0.f;
        float d1 = (er1 < M) ? g_dinv[er1] : 0.f;
        #pragma unroll
        for (int nt = 0; nt < 8; nt++) {
            if (er0 < M)
                *(__half2*)(Y + (size_t)er0 * 128 + nt * 8 + ec) =
                    __floats2half2_rn(acc[rt][nt][0] * d0, acc[rt][nt][1] * d0);
            if (er1 < M)
                *(__half2*)(Y + (size_t)er1 * 128 + nt * 8 + ec) =
                    __floats2half2_rn(acc[rt][nt][2] * d1, acc[rt][nt][3] * d1);
        }
    }
}

// ---------------- aggregation: warp per node, lane owns 4 channels (fp16 gather) ----------------
__global__ void k_agg(const __half* __restrict__ y, const float* __restrict__ bias,
                      float* __restrict__ out) {
    int gwarp = (blockIdx.x * blockDim.x + threadIdx.x) >> 5;
    if (gwarp >= N_NODES) return;
    int lane = threadIdx.x & 31;
    int ch = lane * 4;
    int beg = g_ptr[gwarp], end = g_ptr[gwarp + 1];

    // even/odd accumulator sets break the FMA dependency chain
    float e0 = 0.f, e1 = 0.f, e2 = 0.f, e3 = 0.f;
    float o0 = 0.f, o1 = 0.f, o2 = 0.f, o3 = 0.f;
    for (int e = beg; e < end; e += 32) {
        int n = min(32, end - e);
        int2 ed = (lane < n) ? g_csr[e + lane] : make_int2(0, 0);
        int j = 0;
        for (; j + 1 < n; j += 2) {
            int   s0 = __shfl_sync(0xffffffffu, ed.x, j);
            float w0 = __int_as_float(__shfl_sync(0xffffffffu, ed.y, j));
            int   s1 = __shfl_sync(0xffffffffu, ed.x, j + 1);
            float w1 = __int_as_float(__shfl_sync(0xffffffffu, ed.y, j + 1));
            float2 r0 = *(const float2*)(y + (size_t)s0 * 128 + ch);
            float2 r1 = *(const float2*)(y + (size_t)s1 * 128 + ch);
            float2 p0 = __half22float2(*(__half2*)&r0.x);
            float2 p1 = __half22float2(*(__half2*)&r0.y);
            float2 q0 = __half22float2(*(__half2*)&r1.x);
            float2 q1 = __half22float2(*(__half2*)&r1.y);
            e0 = fmaf(p0.x, w0, e0); e1 = fmaf(p0.y, w0, e1);
            e2 = fmaf(p1.x, w0, e2); e3 = fmaf(p1.y, w0, e3);
            o0 = fmaf(q0.x, w1, o0); o1 = fmaf(q0.y, w1, o1);
            o2 = fmaf(q1.x, w1, o2); o3 = fmaf(q1.y, w1, o3);
        }
        if (j < n) {
            int   s0 = __shfl_sync(0xffffffffu, ed.x, j);
            float w0 = __int_as_float(__shfl_sync(0xffffffffu, ed.y, j));
            float2 r0 = *(const float2*)(y + (size_t)s0 * 128 + ch);
            float2 p0 = __half22float2(*(__half2*)&r0.x);
            float2 p1 = __half22float2(*(__half2*)&r0.y);
            e0 = fmaf(p0.x, w0, e0); e1 = fmaf(p0.y, w0, e1);
            e2 = fmaf(p1.x, w0, e2); e3 = fmaf(p1.y, w0, e3);
        }
    }
    // self loop: +y_i (weight 1 in prescaled space)
    {
        float2 r0 = *(const float2*)(y + (size_t)gwarp * 128 + ch);
        float2 p0 = __half22float2(*(__half2*)&r0.x);
        float2 p1 = __half22float2(*(__half2*)&r0.y);
        e0 += p0.x; e1 += p0.y; e2 += p1.x; e3 += p1.y;
    }
    float a0 = e0 + o0, a1 = e1 + o1, a2 = e2 + o2, a3 = e3 + o3;
    float di = g_dinv[gwarp];
    float4 b = *(const float4*)(bias + ch);
    float4 o;
    o.x = fmaxf(fmaf(di, a0, b.x), 0.f);
    o.y = fmaxf(fmaf(di, a1, b.y), 0.f);
    o.z = fmaxf(fmaf(di, a2, b.z), 0.f);
    o.w = fmaxf(fmaf(di, a3, b.w), 0.f);
    *(float4*)(out + (size_t)gwarp * 128 + ch) = o;
}

// ---------------- pooling: segment_sum over sorted batch ----------------
#define POOL_NB 512
__global__ void k_pool(const float* __restrict__ h, const void* __restrict__ batch) {
    int c = threadIdx.x;
    int start = blockIdx.x * POOL_NB;
    if (start >= N_NODES) return;
    int is64 = g_is64;
    int end = min(start + POOL_NB, N_NODES);
    int cur = load_idx(batch, start, is64);
    float acc = 0.f;
    for (int n = start; n < end; n++) {
        int g = load_idx(batch, n, is64);
        if (g != cur) {
            atomicAdd(&g_pool[cur * HID_CH + c], acc);
            acc = 0.f; cur = g;
        }
        acc += h[(size_t)n * 128 + c];
    }
    atomicAdd(&g_pool[cur * HID_CH + c], acc);
}

// ---------------- classifier + sigmoid ----------------
__global__ void k_final(const float* __restrict__ Wc, const float* __restrict__ bc,
                        float* __restrict__ out) {
    int g = blockIdx.x;
    int c = threadIdx.x;
    float s = bc[c];
    #pragma unroll 4
    for (int k = 0; k < 128; k++)
        s = fmaf(g_pool[g * 128 + k], Wc[k * 64 + c], s);
    out[g * 64 + c] = 1.f / (1.f + expf(-s));
}

// ---------------- launch ----------------
extern "C" void kernel_launch(void* const* d_in, const int* in_sizes, int n_in,
                              void* d_out, int out_size) {
    const float* x     = (const float*)d_in[0];
    const void*  ei    = d_in[1];
    const float* ew    = (const float*)d_in[2];
    const void*  batch = d_in[3];
    const float* W1    = (const float*)d_in[4];
    const float* b1    = (const float*)d_in[5];
    const float* W2    = (const float*)d_in[6];
    const float* b2    = (const float*)d_in[7];
    const float* Wc    = (const float*)d_in[8];
    const float* bc    = (const float*)d_in[9];
    float* out = (float*)d_out;

    cudaFuncSetAttribute(k_gemm_tc, cudaFuncAttributeMaxDynamicSharedMemorySize, SME_TOTAL);

    __half* d_y; cudaGetSymbolAddress((void**)&d_y, g_y16);
    float* d_h;  cudaGetSymbolAddress((void**)&d_h,  g_h);
    __nv_bfloat16 *d_w1hi, *d_w1lo, *d_w2hi, *d_w2lo;
    cudaGetSymbolAddress((void**)&d_w1hi, g_w1hi);
    cudaGetSymbolAddress((void**)&d_w1lo, g_w1lo);
    cudaGetSymbolAddress((void**)&d_w2hi, g_w2hi);
    cudaGetSymbolAddress((void**)&d_w2lo, g_w2lo);

    const int TB = 256;
    const int egrid = (N_EDGES + TB - 1) / TB;
    const int ngrid = (N_NODES + TB - 1) / TB;
    const int nb_scan = (N_NODES + 1023) / 1024;
    const int wgrid = (N_NODES * 32 + TB - 1) / TB;   // warp per node

    // init(+probe) + weight split + CSR build (counts -> scan -> fill -> deg/dinv)
    k_zero<<<ngrid, TB>>>((const int*)ei);
    k_wsplit<<<128, 256>>>(W1, W2);
    k_pass1<<<egrid, TB>>>(ei);
    k_scan1<<<nb_scan, 1024>>>(N_NODES);
    k_scan2<<<1, 32>>>(nb_scan);
    k_scan3<<<ngrid, TB>>>(N_NODES);
    k_fill<<<egrid, TB>>>(ei, ew);
    k_degdinv<<<wgrid, TB>>>();

    const int mma_grid = (N_NODES + 127) / 128;

    // layer 1
    k_gemm_tc<<<mma_grid, 256, SME_TOTAL>>>(x, d_w1hi, d_w1lo, d_y, N_NODES);
    k_agg<<<wgrid, TB>>>(d_y, b1, d_h);
    // layer 2
    k_gemm_tc<<<mma_grid, 256, SME_TOTAL>>>(d_h, d_w2hi, d_w2lo, d_y, N_NODES);
    k_agg<<<wgrid, TB>>>(d_y, b2, d_h);

    // pooling + classifier
    const int pool_grid = (N_NODES + POOL_NB - 1) / POOL_NB;
    k_pool<<<pool_grid, 128>>>(d_h, batch);
    k_final<<<N_GRAPHS, OUT_CH>>>(Wc, bc, out);

    (void)in_sizes; (void)n_in; (void)out_size;
}

// round 7
// speedup vs baseline: 1.0672x; 1.0672x over previous
#include <cuda_runtime.h>
#include <cuda_bf16.h>
#include <cuda_fp16.h>
#include <math.h>
#include <stdint.h>

// Problem constants (match reference)
#define N_NODES  100000
#define N_EDGES  3200000
#define IN_CH    128
#define HID_CH   128
#define OUT_CH   64
#define N_GRAPHS 128

// ---------------- scratch (device globals; no allocation allowed) ----------------
__device__ float g_deg[N_NODES];
__device__ float g_dinv[N_NODES];
__device__ int   g_cnt[N_NODES];
__device__ int   g_ptr[N_NODES + 1];
__device__ int   g_cursor[N_NODES];
__device__ int   g_bsum[128];
__device__ int   g_boff[128];
__device__ int2  g_csr[N_EDGES];                 // {src, __float_as_int(raw edge weight)}
__device__ __half g_y16[N_NODES * HID_CH];       // dinv-prescaled GEMM output (gather operand)
__device__ float g_h[N_NODES * HID_CH];          // post-aggregation activations (fp32)
__device__ float g_pool[N_GRAPHS * HID_CH];
__device__ int   g_is64;                         // 1 if index tensors are int64
// bf16-split transposed weights: wt[n*128+k] = W[k*128+n]
__device__ __nv_bfloat16 g_w1hi[HID_CH * IN_CH];
__device__ __nv_bfloat16 g_w1lo[HID_CH * IN_CH];
__device__ __nv_bfloat16 g_w2hi[HID_CH * HID_CH];
__device__ __nv_bfloat16 g_w2lo[HID_CH * HID_CH];

__device__ __forceinline__ uint32_t smem_u32(const void* p) {
    uint32_t a;
    asm("{ .reg .u64 t; cvta.to.shared.u64 t, %1; cvt.u32.u64 %0, t; }" : "=r"(a) : "l"(p));
    return a;
}

// ---------------- index accessor (int32 or int64) ----------------
__device__ __forceinline__ int load_idx(const void* p, long long i, int is64) {
    if (is64) return (int)((const long long*)p)[i];
    return ((const int*)p)[i];
}

// ---------------- init + dtype probe (merged) ----------------
__global__ void k_zero(const int* ei_probe) {
    int i = blockIdx.x * blockDim.x + threadIdx.x;
    if (i == 0) {
        int nz = 0;
        for (int j = 0; j < 64; j++) nz |= ei_probe[2 * j + 1];
        g_is64 = (nz == 0) ? 1 : 0;
    }
    if (i < N_NODES) { g_deg[i] = 0.f; g_cnt[i] = 0; }
    if (i < N_GRAPHS * HID_CH) g_pool[i] = 0.f;
}

// ---------------- weight transpose + bf16 split (both layers, one launch) ----------------
__global__ void k_wsplit(const float* __restrict__ W1, const float* __restrict__ W2) {
    int bid = blockIdx.x;
    const float* W = (bid < 64) ? W1 : W2;
    __nv_bfloat16* hi = (bid < 64) ? g_w1hi : g_w2hi;
    __nv_bfloat16* lo = (bid < 64) ? g_w1lo : g_w2lo;
    int i = (bid & 63) * 256 + threadIdx.x;      // i = k*128 + n
    int k = i >> 7, n = i & 127;
    float w = W[i];
    __nv_bfloat16 h = __float2bfloat16_rn(w);
    __nv_bfloat16 l = __float2bfloat16_rn(w - __bfloat162float(h));
    hi[n * 128 + k] = h;
    lo[n * 128 + k] = l;
}

// ---------------- pass 1: degree + per-target edge counts (R5-proven) ----------------
__global__ void k_pass1(const void* __restrict__ ei, const float* __restrict__ w) {
    int e = blockIdx.x * blockDim.x + threadIdx.x;
    if (e >= N_EDGES) return;
    int is64 = g_is64;
    int c = load_idx(ei, (long long)N_EDGES + e, is64);
    atomicAdd(&g_deg[c], w[e]);
    atomicAdd(&g_cnt[c], 1);
}

__global__ void k_dinv() {
    int i = blockIdx.x * blockDim.x + threadIdx.x;
    if (i >= N_NODES) return;
    g_dinv[i] = rsqrtf(g_deg[i] + 1.0f);
}

// ---------------- exclusive scan of counts -> g_ptr ----------------
__global__ void k_scan1(int n) {
    __shared__ int sm[1024];
    int i = blockIdx.x * 1024 + threadIdx.x;
    int v = (i < n) ? g_cnt[i] : 0;
    sm[threadIdx.x] = v;
    __syncthreads();
    for (int off = 1; off < 1024; off <<= 1) {
        int t = (threadIdx.x >= off) ? sm[threadIdx.x - off] : 0;
        __syncthreads();
        sm[threadIdx.x] += t;
        __syncthreads();
    }
    if (i < n) g_ptr[i + 1] = sm[threadIdx.x];
    if (threadIdx.x == 1023) g_bsum[blockIdx.x] = sm[1023];
}

__global__ void k_scan2(int nb) {
    if (threadIdx.x == 0 && blockIdx.x == 0) {
        int acc = 0;
        for (int b = 0; b < nb; b++) { int t = g_bsum[b]; g_boff[b] = acc; acc += t; }
    }
}

// final ptr + cursor init in one pass: cursor[i] = final_ptr[i+1] - cnt[i]
__global__ void k_scan3(int n) {
    int i = blockIdx.x * blockDim.x + threadIdx.x;
    if (i == 0) g_ptr[0] = 0;
    if (i < n) {
        int v = g_ptr[i + 1] + g_boff[i >> 10];
        g_ptr[i + 1] = v;
        g_cursor[i] = v - g_cnt[i];
    }
}

// ---------------- pass 2: fill CSR with (src, raw weight) — no random reads ----------------
__global__ void k_fill(const void* __restrict__ ei, const float* __restrict__ w) {
    int e = blockIdx.x * blockDim.x + threadIdx.x;
    if (e >= N_EDGES) return;
    int is64 = g_is64;
    int r = load_idx(ei, e, is64);
    int c = load_idx(ei, (long long)N_EDGES + e, is64);
    int p = atomicAdd(&g_cursor[c], 1);
    g_csr[p] = make_int2(r, __float_as_int(w[e]));
}

// ---------------- mma.sync GEMM: Y[M,128] = fp16(dinv .* (A[M,128] @ W)) (3x bf16 split) ----------------
// R5-proven: Block = 128x128, 256 threads (8 warps). Warp w: rows w*16..w*16+15, all 128 cols.
#define PADK 136
#define SME_TOTAL (4 * 128 * PADK * 2)

__global__ __launch_bounds__(256, 1) void k_gemm_tc(const float* __restrict__ A,
                                                    const __nv_bfloat16* __restrict__ wt_hi,
                                                    const __nv_bfloat16* __restrict__ wt_lo,
                                                    __half* __restrict__ Y, int M) {
    extern __shared__ char smem_raw[];
    __nv_bfloat16* Ah = (__nv_bfloat16*)smem_raw;
    __nv_bfloat16* Al = Ah + 128 * PADK;
    __nv_bfloat16* Bh = Al + 128 * PADK;
    __nv_bfloat16* Bl = Bh + 128 * PADK;
    int tid = threadIdx.x;
    int wid = tid >> 5, lane = tid & 31;
    int row0 = blockIdx.x * 128;

    // Load A [128x128 f32] -> hi/lo bf16 split
    for (int g = tid; g < 128 * 32; g += 256) {
        int r = g >> 5, c4 = (g & 31) * 4;
        int gr = row0 + r;
        float4 v = make_float4(0.f, 0.f, 0.f, 0.f);
        if (gr < M) v = ((const float4*)(A + (size_t)gr * 128))[c4 >> 2];
        __nv_bfloat16 h0 = __float2bfloat16_rn(v.x), h1 = __float2bfloat16_rn(v.y);
        __nv_bfloat16 h2 = __float2bfloat16_rn(v.z), h3 = __float2bfloat16_rn(v.w);
        __nv_bfloat16* ah = Ah + r * PADK + c4;
        __nv_bfloat16* al = Al + r * PADK + c4;
        ah[0] = h0; ah[1] = h1; ah[2] = h2; ah[3] = h3;
        al[0] = __float2bfloat16_rn(v.x - __bfloat162float(h0));
        al[1] = __float2bfloat16_rn(v.y - __bfloat162float(h1));
        al[2] = __float2bfloat16_rn(v.z - __bfloat162float(h2));
        al[3] = __float2bfloat16_rn(v.w - __bfloat162float(h3));
    }
    // Load B (pre-split transposed weights): 16-byte vectors
    for (int g = tid; g < 128 * 16; g += 256) {
        int r = g >> 4, c8 = (g & 15) * 8;
        *(float4*)(Bh + r * PADK + c8) = *(const float4*)(wt_hi + r * 128 + c8);
        *(float4*)(Bl + r * PADK + c8) = *(const float4*)(wt_lo + r * 128 + c8);
    }
    __syncthreads();

    float acc[16][4];
    #pragma unroll
    for (int nt = 0; nt < 16; nt++)
        #pragma unroll
        for (int j = 0; j < 4; j++) acc[nt][j] = 0.f;

    int rowA = wid * 16;
    int a_r = rowA + (lane & 15);
    int a_c = (lane >> 4) * 8;
    int b_r = (lane & 7);
    int b_c = ((lane >> 3) & 1) * 8;

    const __nv_bfloat16* Aptr[3] = {Ah, Ah, Al};
    const __nv_bfloat16* Bptr[3] = {Bh, Bl, Bh};

    #pragma unroll
    for (int pass = 0; pass < 3; pass++) {
        uint32_t abase = smem_u32(Aptr[pass] + a_r * PADK + a_c);
        uint32_t bbase = smem_u32(Bptr[pass] + b_r * PADK + b_c);
        #pragma unroll
        for (int kc = 0; kc < 8; kc++) {
            uint32_t a0, a1, a2, a3;
            asm volatile("ldmatrix.sync.aligned.m8n8.x4.shared.b16 {%0,%1,%2,%3}, [%4];"
                         : "=r"(a0), "=r"(a1), "=r"(a2), "=r"(a3)
                         : "r"(abase + kc * 32));
            #pragma unroll
            for (int nt = 0; nt < 16; nt++) {
                uint32_t b0, b1;
                asm volatile("ldmatrix.sync.aligned.m8n8.x2.shared.b16 {%0,%1}, [%2];"
                             : "=r"(b0), "=r"(b1)
                             : "r"(bbase + (uint32_t)(nt * 8 * PADK * 2) + kc * 32));
                asm volatile("mma.sync.aligned.m16n8k16.row.col.f32.bf16.bf16.f32 "
                             "{%0,%1,%2,%3}, {%4,%5,%6,%7}, {%8,%9}, {%0,%1,%2,%3};"
                             : "+f"(acc[nt][0]), "+f"(acc[nt][1]), "+f"(acc[nt][2]), "+f"(acc[nt][3])
                             : "r"(a0), "r"(a1), "r"(a2), "r"(a3), "r"(b0), "r"(b1));
            }
        }
    }

    // Epilogue: scale by dinv[row], pack to fp16.
    int er0 = row0 + rowA + (lane >> 2);
    int er1 = er0 + 8;
    int ec = (lane & 3) * 2;
    float d0 = (er0 < M) ? g_dinv[er0] : 0.f;
    float d1 = (er1 < M) ? g_dinv[er1] : 0.f;
    #pragma unroll
    for (int nt = 0; nt < 16; nt++) {
        if (er0 < M)
            *(__half2*)(Y + (size_t)er0 * 128 + nt * 8 + ec) =
                __floats2half2_rn(acc[nt][0] * d0, acc[nt][1] * d0);
        if (er1 < M)
            *(__half2*)(Y + (size_t)er1 * 128 + nt * 8 + ec) =
                __floats2half2_rn(acc[nt][2] * d1, acc[nt][3] * d1);
    }
}

// ---------------- aggregation: warp per node, lane owns 4 channels (R5-proven) ----------------
__global__ void k_agg(const __half* __restrict__ y, const float* __restrict__ bias,
                      float* __restrict__ out) {
    int gwarp = (blockIdx.x * blockDim.x + threadIdx.x) >> 5;
    if (gwarp >= N_NODES) return;
    int lane = threadIdx.x & 31;
    int ch = lane * 4;
    int beg = g_ptr[gwarp], end = g_ptr[gwarp + 1];

    float a0 = 0.f, a1 = 0.f, a2 = 0.f, a3 = 0.f;
    for (int e = beg; e < end; e += 32) {
        int n = min(32, end - e);
        int2 ed = (lane < n) ? g_csr[e + lane] : make_int2(0, 0);
        int j = 0;
        for (; j + 1 < n; j += 2) {
            int   s0 = __shfl_sync(0xffffffffu, ed.x, j);
            float w0 = __int_as_float(__shfl_sync(0xffffffffu, ed.y, j));
            int   s1 = __shfl_sync(0xffffffffu, ed.x, j + 1);
            float w1 = __int_as_float(__shfl_sync(0xffffffffu, ed.y, j + 1));
            float2 r0 = *(const float2*)(y + (size_t)s0 * 128 + ch);
            float2 r1 = *(const float2*)(y + (size_t)s1 * 128 + ch);
            float2 p0 = __half22float2(*(__half2*)&r0.x);
            float2 p1 = __half22float2(*(__half2*)&r0.y);
            float2 q0 = __half22float2(*(__half2*)&r1.x);
            float2 q1 = __half22float2(*(__half2*)&r1.y);
            a0 = fmaf(p0.x, w0, a0); a1 = fmaf(p0.y, w0, a1);
            a2 = fmaf(p1.x, w0, a2); a3 = fmaf(p1.y, w0, a3);
            a0 = fmaf(q0.x, w1, a0); a1 = fmaf(q0.y, w1, a1);
            a2 = fmaf(q1.x, w1, a2); a3 = fmaf(q1.y, w1, a3);
        }
        if (j < n) {
            int   s0 = __shfl_sync(0xffffffffu, ed.x, j);
            float w0 = __int_as_float(__shfl_sync(0xffffffffu, ed.y, j));
            float2 r0 = *(const float2*)(y + (size_t)s0 * 128 + ch);
            float2 p0 = __half22float2(*(__half2*)&r0.x);
            float2 p1 = __half22float2(*(__half2*)&r0.y);
            a0 = fmaf(p0.x, w0, a0); a1 = fmaf(p0.y, w0, a1);
            a2 = fmaf(p1.x, w0, a2); a3 = fmaf(p1.y, w0, a3);
        }
    }
    // self loop: +y_i (weight 1 in prescaled space)
    {
        float2 r0 = *(const float2*)(y + (size_t)gwarp * 128 + ch);
        float2 p0 = __half22float2(*(__half2*)&r0.x);
        float2 p1 = __half22float2(*(__half2*)&r0.y);
        a0 += p0.x; a1 += p0.y; a2 += p1.x; a3 += p1.y;
    }
    float di = g_dinv[gwarp];
    float4 b = *(const float4*)(bias + ch);
    float4 o;
    o.x = fmaxf(fmaf(di, a0, b.x), 0.f);
    o.y = fmaxf(fmaf(di, a1, b.y), 0.f);
    o.z = fmaxf(fmaf(di, a2, b.z), 0.f);
    o.w = fmaxf(fmaf(di, a3, b.w), 0.f);
    *(float4*)(out + (size_t)gwarp * 128 + ch) = o;
}

// ---------------- pooling: segment_sum over sorted batch (more blocks) ----------------
#define POOL_NB 128
__global__ void k_pool(const float* __restrict__ h, const void* __restrict__ batch) {
    int c = threadIdx.x;
    int start = blockIdx.x * POOL_NB;
    if (start >= N_NODES) return;
    int is64 = g_is64;
    int end = min(start + POOL_NB, N_NODES);
    int cur = load_idx(batch, start, is64);
    float acc = 0.f;
    for (int n = start; n < end; n++) {
        int g = load_idx(batch, n, is64);
        if (g != cur) {
            atomicAdd(&g_pool[cur * HID_CH + c], acc);
            acc = 0.f; cur = g;
        }
        acc += h[(size_t)n * 128 + c];
    }
    atomicAdd(&g_pool[cur * HID_CH + c], acc);
}

// ---------------- classifier + sigmoid ----------------
__global__ void k_final(const float* __restrict__ Wc, const float* __restrict__ bc,
                        float* __restrict__ out) {
    int g = blockIdx.x;
    int c = threadIdx.x;
    float s = bc[c];
    #pragma unroll 4
    for (int k = 0; k < 128; k++)
        s = fmaf(g_pool[g * 128 + k], Wc[k * 64 + c], s);
    out[g * 64 + c] = 1.f / (1.f + expf(-s));
}

// ---------------- launch ----------------
extern "C" void kernel_launch(void* const* d_in, const int* in_sizes, int n_in,
                              void* d_out, int out_size) {
    const float* x     = (const float*)d_in[0];
    const void*  ei    = d_in[1];
    const float* ew    = (const float*)d_in[2];
    const void*  batch = d_in[3];
    const float* W1    = (const float*)d_in[4];
    const float* b1    = (const float*)d_in[5];
    const float* W2    = (const float*)d_in[6];
    const float* b2    = (const float*)d_in[7];
    const float* Wc    = (const float*)d_in[8];
    const float* bc    = (const float*)d_in[9];
    float* out = (float*)d_out;

    cudaFuncSetAttribute(k_gemm_tc, cudaFuncAttributeMaxDynamicSharedMemorySize, SME_TOTAL);

    __half* d_y; cudaGetSymbolAddress((void**)&d_y, g_y16);
    float* d_h;  cudaGetSymbolAddress((void**)&d_h,  g_h);
    __nv_bfloat16 *d_w1hi, *d_w1lo, *d_w2hi, *d_w2lo;
    cudaGetSymbolAddress((void**)&d_w1hi, g_w1hi);
    cudaGetSymbolAddress((void**)&d_w1lo, g_w1lo);
    cudaGetSymbolAddress((void**)&d_w2hi, g_w2hi);
    cudaGetSymbolAddress((void**)&d_w2lo, g_w2lo);

    const int TB = 256;
    const int egrid = (N_EDGES + TB - 1) / TB;
    const int ngrid = (N_NODES + TB - 1) / TB;
    const int nb_scan = (N_NODES + 1023) / 1024;
    const int wgrid = (N_NODES * 32 + TB - 1) / TB;   // warp per node

    // init(+probe) + weight split + CSR build
    k_zero<<<ngrid, TB>>>((const int*)ei);
    k_wsplit<<<128, 256>>>(W1, W2);
    k_pass1<<<egrid, TB>>>(ei, ew);
    k_dinv<<<ngrid, TB>>>();
    k_scan1<<<nb_scan, 1024>>>(N_NODES);
    k_scan2<<<1, 32>>>(nb_scan);
    k_scan3<<<ngrid, TB>>>(N_NODES);
    k_fill<<<egrid, TB>>>(ei, ew);

    const int mma_grid = (N_NODES + 127) / 128;

    // layer 1
    k_gemm_tc<<<mma_grid, 256, SME_TOTAL>>>(x, d_w1hi, d_w1lo, d_y, N_NODES);
    k_agg<<<wgrid, TB>>>(d_y, b1, d_h);
    // layer 2
    k_gemm_tc<<<mma_grid, 256, SME_TOTAL>>>(d_h, d_w2hi, d_w2lo, d_y, N_NODES);
    k_agg<<<wgrid, TB>>>(d_y, b2, d_h);

    // pooling + classifier
    const int pool_grid = (N_NODES + POOL_NB - 1) / POOL_NB;
    k_pool<<<pool_grid, 128>>>(d_h, batch);
    k_final<<<N_GRAPHS, OUT_CH>>>(Wc, bc, out);

    (void)in_sizes; (void)n_in; (void)out_size;
}

// round 8
// speedup vs baseline: 1.7268x; 1.6180x over previous
#include <cuda_runtime.h>
#include <cuda_bf16.h>
#include <cuda_fp16.h>
#include <math.h>
#include <stdint.h>

// Problem constants (match reference)
#define N_NODES  100000
#define N_EDGES  3200000
#define IN_CH    128
#define HID_CH   128
#define OUT_CH   64
#define N_GRAPHS 128

// ---------------- scratch (device globals; no allocation allowed) ----------------
__device__ float g_deg[N_NODES];
__device__ float g_dinv[N_NODES];
__device__ int   g_cnt[N_NODES];
__device__ int   g_ptr[N_NODES + 1];
__device__ int   g_cursor[N_NODES];
__device__ int   g_bsum[128];
__device__ int   g_boff[128];
__device__ int2  g_csr[N_EDGES];                 // {src, __float_as_int(raw edge weight)}
__device__ __half g_y16[N_NODES * HID_CH];       // dinv-prescaled GEMM output (gather operand)
__device__ float g_h[N_NODES * HID_CH];          // post-aggregation activations (fp32)
__device__ float g_pool[N_GRAPHS * HID_CH];
__device__ int   g_is64;                         // 1 if index tensors are int64
// bf16-split transposed weights: wt[n*128+k] = W[k*128+n]
__device__ __nv_bfloat16 g_w1hi[HID_CH * IN_CH];
__device__ __nv_bfloat16 g_w1lo[HID_CH * IN_CH];
__device__ __nv_bfloat16 g_w2hi[HID_CH * HID_CH];
__device__ __nv_bfloat16 g_w2lo[HID_CH * HID_CH];

__device__ __forceinline__ uint32_t smem_u32(const void* p) {
    uint32_t a;
    asm("{ .reg .u64 t; cvta.to.shared.u64 t, %1; cvt.u32.u64 %0, t; }" : "=r"(a) : "l"(p));
    return a;
}

// ---------------- index accessor (int32 or int64) ----------------
__device__ __forceinline__ int load_idx(const void* p, long long i, int is64) {
    if (is64) return (int)((const long long*)p)[i];
    return ((const int*)p)[i];
}

__global__ void k_detect(const int* p) {
    if (threadIdx.x == 0 && blockIdx.x == 0) {
        int nz = 0;
        for (int i = 0; i < 64; i++) nz |= p[2 * i + 1];
        g_is64 = (nz == 0) ? 1 : 0;
    }
}

// ---------------- weight transpose + bf16 split ----------------
__global__ void k_wsplit(const float* __restrict__ W, __nv_bfloat16* __restrict__ hi,
                         __nv_bfloat16* __restrict__ lo) {
    int i = blockIdx.x * blockDim.x + threadIdx.x;   // i = k*128 + n
    if (i >= 128 * 128) return;
    int k = i >> 7, n = i & 127;
    float w = W[i];
    __nv_bfloat16 h = __float2bfloat16_rn(w);
    __nv_bfloat16 l = __float2bfloat16_rn(w - __bfloat162float(h));
    hi[n * 128 + k] = h;
    lo[n * 128 + k] = l;
}

// ---------------- init ----------------
__global__ void k_zero() {
    int i = blockIdx.x * blockDim.x + threadIdx.x;
    if (i < N_NODES) { g_deg[i] = 0.f; g_cnt[i] = 0; }
    if (i < N_GRAPHS * HID_CH) g_pool[i] = 0.f;
}

// ---------------- pass 1: degree + per-target edge counts ----------------
__global__ void k_pass1(const void* __restrict__ ei, const float* __restrict__ w) {
    int e = blockIdx.x * blockDim.x + threadIdx.x;
    if (e >= N_EDGES) return;
    int is64 = g_is64;
    int c = load_idx(ei, (long long)N_EDGES + e, is64);
    atomicAdd(&g_deg[c], w[e]);
    atomicAdd(&g_cnt[c], 1);
}

__global__ void k_dinv() {
    int i = blockIdx.x * blockDim.x + threadIdx.x;
    if (i >= N_NODES) return;
    g_dinv[i] = rsqrtf(g_deg[i] + 1.0f);
}

// ---------------- exclusive scan of counts -> g_ptr ----------------
__global__ void k_scan1(int n) {
    __shared__ int sm[1024];
    int i = blockIdx.x * 1024 + threadIdx.x;
    int v = (i < n) ? g_cnt[i] : 0;
    sm[threadIdx.x] = v;
    __syncthreads();
    for (int off = 1; off < 1024; off <<= 1) {
        int t = (threadIdx.x >= off) ? sm[threadIdx.x - off] : 0;
        __syncthreads();
        sm[threadIdx.x] += t;
        __syncthreads();
    }
    if (i < n) g_ptr[i + 1] = sm[threadIdx.x];
    if (threadIdx.x == 1023) g_bsum[blockIdx.x] = sm[1023];
}

__global__ void k_scan2(int nb) {
    if (threadIdx.x == 0 && blockIdx.x == 0) {
        int acc = 0;
        for (int b = 0; b < nb; b++) { int t = g_bsum[b]; g_boff[b] = acc; acc += t; }
    }
}

__global__ void k_scan3(int n) {
    int i = blockIdx.x * blockDim.x + threadIdx.x;
    if (i == 0) g_ptr[0] = 0;
    if (i < n) g_ptr[i + 1] += g_boff[i >> 10];
}

__global__ void k_cursor(int n) {
    int i = blockIdx.x * blockDim.x + threadIdx.x;
    if (i < n) g_cursor[i] = g_ptr[i];
}

// ---------------- pass 2: fill CSR with (src, raw weight) — no random reads ----------------
__global__ void k_fill(const void* __restrict__ ei, const float* __restrict__ w) {
    int e = blockIdx.x * blockDim.x + threadIdx.x;
    if (e >= N_EDGES) return;
    int is64 = g_is64;
    int r = load_idx(ei, e, is64);
    int c = load_idx(ei, (long long)N_EDGES + e, is64);
    int p = atomicAdd(&g_cursor[c], 1);
    g_csr[p] = make_int2(r, __float_as_int(w[e]));
}

// ---------------- mma.sync GEMM: Y[M,128] = fp16(dinv .* (A[M,128] @ W)) (3x bf16 split) ----------------
// Block = 128x128, 256 threads (8 warps). Warp w: rows w*16..w*16+15, all 128 cols.
// smem: Ah, Al, Bs each [128][PADK] bf16 -> 104,448 B total -> 2 blocks/SM.
// Pass order: (AhiBhi, AloBhi) with Bs=Whi, then reload Bs=Wlo, then AhiBlo.
#define PADK 136
#define SME_TOTAL (3 * 128 * PADK * 2)

__global__ __launch_bounds__(256, 2) void k_gemm_tc(const float* __restrict__ A,
                                                    const __nv_bfloat16* __restrict__ wt_hi,
                                                    const __nv_bfloat16* __restrict__ wt_lo,
                                                    __half* __restrict__ Y, int M) {
    extern __shared__ char smem_raw[];
    __nv_bfloat16* Ah = (__nv_bfloat16*)smem_raw;
    __nv_bfloat16* Al = Ah + 128 * PADK;
    __nv_bfloat16* Bs = Al + 128 * PADK;
    int tid = threadIdx.x;
    int wid = tid >> 5, lane = tid & 31;
    int row0 = blockIdx.x * 128;

    // Load A [128x128 f32] -> hi/lo bf16 split
    for (int g = tid; g < 128 * 32; g += 256) {
        int r = g >> 5, c4 = (g & 31) * 4;
        int gr = row0 + r;
        float4 v = make_float4(0.f, 0.f, 0.f, 0.f);
        if (gr < M) v = ((const float4*)(A + (size_t)gr * 128))[c4 >> 2];
        __nv_bfloat16 h0 = __float2bfloat16_rn(v.x), h1 = __float2bfloat16_rn(v.y);
        __nv_bfloat16 h2 = __float2bfloat16_rn(v.z), h3 = __float2bfloat16_rn(v.w);
        __nv_bfloat16* ah = Ah + r * PADK + c4;
        __nv_bfloat16* al = Al + r * PADK + c4;
        ah[0] = h0; ah[1] = h1; ah[2] = h2; ah[3] = h3;
        al[0] = __float2bfloat16_rn(v.x - __bfloat162float(h0));
        al[1] = __float2bfloat16_rn(v.y - __bfloat162float(h1));
        al[2] = __float2bfloat16_rn(v.z - __bfloat162float(h2));
        al[3] = __float2bfloat16_rn(v.w - __bfloat162float(h3));
    }
    // Load B = W_hi (pre-split transposed weights)
    for (int g = tid; g < 128 * 16; g += 256) {
        int r = g >> 4, c8 = (g & 15) * 8;
        *(float4*)(Bs + r * PADK + c8) = *(const float4*)(wt_hi + r * 128 + c8);
    }
    __syncthreads();

    float acc[16][4];
    #pragma unroll
    for (int nt = 0; nt < 16; nt++)
        #pragma unroll
        for (int j = 0; j < 4; j++) acc[nt][j] = 0.f;

    int rowA = wid * 16;
    int a_r = rowA + (lane & 15);
    int a_c = (lane >> 4) * 8;
    int b_r = (lane & 7);
    int b_c = ((lane >> 3) & 1) * 8;

    uint32_t abase_h = smem_u32(Ah + a_r * PADK + a_c);
    uint32_t abase_l = smem_u32(Al + a_r * PADK + a_c);
    uint32_t bbase   = smem_u32(Bs + b_r * PADK + b_c);

    // passes with Bs = W_hi: AhiBhi then AloBhi
    #pragma unroll
    for (int pass = 0; pass < 2; pass++) {
        uint32_t abase = (pass == 0) ? abase_h : abase_l;
        #pragma unroll
        for (int kc = 0; kc < 8; kc++) {
            uint32_t a0, a1, a2, a3;
            asm volatile("ldmatrix.sync.aligned.m8n8.x4.shared.b16 {%0,%1,%2,%3}, [%4];"
                         : "=r"(a0), "=r"(a1), "=r"(a2), "=r"(a3)
                         : "r"(abase + kc * 32));
            #pragma unroll
            for (int nt = 0; nt < 16; nt++) {
                uint32_t b0, b1;
                asm volatile("ldmatrix.sync.aligned.m8n8.x2.shared.b16 {%0,%1}, [%2];"
                             : "=r"(b0), "=r"(b1)
                             : "r"(bbase + (uint32_t)(nt * 8 * PADK * 2) + kc * 32));
                asm volatile("mma.sync.aligned.m16n8k16.row.col.f32.bf16.bf16.f32 "
                             "{%0,%1,%2,%3}, {%4,%5,%6,%7}, {%8,%9}, {%0,%1,%2,%3};"
                             : "+f"(acc[nt][0]), "+f"(acc[nt][1]), "+f"(acc[nt][2]), "+f"(acc[nt][3])
                             : "r"(a0), "r"(a1), "r"(a2), "r"(a3), "r"(b0), "r"(b1));
            }
        }
    }

    // swap B to W_lo
    __syncthreads();
    for (int g = tid; g < 128 * 16; g += 256) {
        int r = g >> 4, c8 = (g & 15) * 8;
        *(float4*)(Bs + r * PADK + c8) = *(const float4*)(wt_lo + r * 128 + c8);
    }
    __syncthreads();

    // pass AhiBlo
    #pragma unroll
    for (int kc = 0; kc < 8; kc++) {
        uint32_t a0, a1, a2, a3;
        asm volatile("ldmatrix.sync.aligned.m8n8.x4.shared.b16 {%0,%1,%2,%3}, [%4];"
                     : "=r"(a0), "=r"(a1), "=r"(a2), "=r"(a3)
                     : "r"(abase_h + kc * 32));
        #pragma unroll
        for (int nt = 0; nt < 16; nt++) {
            uint32_t b0, b1;
            asm volatile("ldmatrix.sync.aligned.m8n8.x2.shared.b16 {%0,%1}, [%2];"
                         : "=r"(b0), "=r"(b1)
                         : "r"(bbase + (uint32_t)(nt * 8 * PADK * 2) + kc * 32));
            asm volatile("mma.sync.aligned.m16n8k16.row.col.f32.bf16.bf16.f32 "
                         "{%0,%1,%2,%3}, {%4,%5,%6,%7}, {%8,%9}, {%0,%1,%2,%3};"
                         : "+f"(acc[nt][0]), "+f"(acc[nt][1]), "+f"(acc[nt][2]), "+f"(acc[nt][3])
                         : "r"(a0), "r"(a1), "r"(a2), "r"(a3), "r"(b0), "r"(b1));
        }
    }

    // Epilogue: scale by dinv[row], pack to fp16.
    int er0 = row0 + rowA + (lane >> 2);
    int er1 = er0 + 8;
    int ec = (lane & 3) * 2;
    float d0 = (er0 < M) ? g_dinv[er0] : 0.f;
    float d1 = (er1 < M) ? g_dinv[er1] : 0.f;
    #pragma unroll
    for (int nt = 0; nt < 16; nt++) {
        if (er0 < M)
            *(__half2*)(Y + (size_t)er0 * 128 + nt * 8 + ec) =
                __floats2half2_rn(acc[nt][0] * d0, acc[nt][1] * d0);
        if (er1 < M)
            *(__half2*)(Y + (size_t)er1 * 128 + nt * 8 + ec) =
                __floats2half2_rn(acc[nt][2] * d1, acc[nt][3] * d1);
    }
}

// ---------------- core aggregation for one node (warp-collective), returns float4 ----------------
__device__ __forceinline__ float4 agg_node(const __half* __restrict__ y, int node, int lane, int ch) {
    int beg = g_ptr[node], end = g_ptr[node + 1];
    float a0 = 0.f, a1 = 0.f, a2 = 0.f, a3 = 0.f;
    for (int e = beg; e < end; e += 32) {
        int n = min(32, end - e);
        int2 ed = (lane < n) ? g_csr[e + lane] : make_int2(0, 0);
        int j = 0;
        for (; j + 1 < n; j += 2) {
            int   s0 = __shfl_sync(0xffffffffu, ed.x, j);
            float w0 = __int_as_float(__shfl_sync(0xffffffffu, ed.y, j));
            int   s1 = __shfl_sync(0xffffffffu, ed.x, j + 1);
            float w1 = __int_as_float(__shfl_sync(0xffffffffu, ed.y, j + 1));
            float2 r0 = *(const float2*)(y + (size_t)s0 * 128 + ch);
            float2 r1 = *(const float2*)(y + (size_t)s1 * 128 + ch);
            float2 p0 = __half22float2(*(__half2*)&r0.x);
            float2 p1 = __half22float2(*(__half2*)&r0.y);
            float2 q0 = __half22float2(*(__half2*)&r1.x);
            float2 q1 = __half22float2(*(__half2*)&r1.y);
            a0 = fmaf(p0.x, w0, a0); a1 = fmaf(p0.y, w0, a1);
            a2 = fmaf(p1.x, w0, a2); a3 = fmaf(p1.y, w0, a3);
            a0 = fmaf(q0.x, w1, a0); a1 = fmaf(q0.y, w1, a1);
            a2 = fmaf(q1.x, w1, a2); a3 = fmaf(q1.y, w1, a3);
        }
        if (j < n) {
            int   s0 = __shfl_sync(0xffffffffu, ed.x, j);
            float w0 = __int_as_float(__shfl_sync(0xffffffffu, ed.y, j));
            float2 r0 = *(const float2*)(y + (size_t)s0 * 128 + ch);
            float2 p0 = __half22float2(*(__half2*)&r0.x);
            float2 p1 = __half22float2(*(__half2*)&r0.y);
            a0 = fmaf(p0.x, w0, a0); a1 = fmaf(p0.y, w0, a1);
            a2 = fmaf(p1.x, w0, a2); a3 = fmaf(p1.y, w0, a3);
        }
    }
    // self loop: +y_i (weight 1 in prescaled space)
    float2 r0 = *(const float2*)(y + (size_t)node * 128 + ch);
    float2 p0 = __half22float2(*(__half2*)&r0.x);
    float2 p1 = __half22float2(*(__half2*)&r0.y);
    a0 += p0.x; a1 += p0.y; a2 += p1.x; a3 += p1.y;
    return make_float4(a0, a1, a2, a3);
}

// ---------------- aggregation layer 1: write fp32 h ----------------
__global__ void k_agg(const __half* __restrict__ y, const float* __restrict__ bias,
                      float* __restrict__ out) {
    int node = (blockIdx.x * blockDim.x + threadIdx.x) >> 5;
    if (node >= N_NODES) return;
    int lane = threadIdx.x & 31;
    int ch = lane * 4;
    float4 a = agg_node(y, node, lane, ch);
    float di = g_dinv[node];
    float4 b = *(const float4*)(bias + ch);
    float4 o;
    o.x = fmaxf(fmaf(di, a.x, b.x), 0.f);
    o.y = fmaxf(fmaf(di, a.y, b.y), 0.f);
    o.z = fmaxf(fmaf(di, a.z, b.z), 0.f);
    o.w = fmaxf(fmaf(di, a.w, b.w), 0.f);
    *(float4*)(out + (size_t)node * 128 + ch) = o;
}

// ---------------- aggregation layer 2 fused with pooling ----------------
// Block = 8 warps = 8 consecutive nodes. Accumulate relu'd rows into per-block
// smem when all nodes share a graph (the common case), else direct atomics.
__global__ void k_agg_pool(const __half* __restrict__ y, const float* __restrict__ bias,
                           const void* __restrict__ batch) {
    __shared__ float pacc[128];
    __shared__ int   sg[8];
    int tid = threadIdx.x;
    int wid = tid >> 5, lane = tid & 31;
    int node = blockIdx.x * 8 + wid;
    bool valid = node < N_NODES;
    int ch = lane * 4;

    int gid = -1;
    if (valid) gid = load_idx(batch, node, g_is64);
    if (lane == 0) sg[wid] = gid;
    if (tid < 128) pacc[tid] = 0.f;

    float4 o = make_float4(0.f, 0.f, 0.f, 0.f);
    if (valid) {
        float4 a = agg_node(y, node, lane, ch);
        float di = g_dinv[node];
        float4 b = *(const float4*)(bias + ch);
        o.x = fmaxf(fmaf(di, a.x, b.x), 0.f);
        o.y = fmaxf(fmaf(di, a.y, b.y), 0.f);
        o.z = fmaxf(fmaf(di, a.z, b.z), 0.f);
        o.w = fmaxf(fmaf(di, a.w, b.w), 0.f);
    }
    __syncthreads();

    int g0 = sg[0];
    bool uni = true;
    #pragma unroll
    for (int w = 1; w < 8; w++) uni = uni && (sg[w] == g0 || sg[w] < 0);

    if (uni) {
        if (valid) {
            atomicAdd(&pacc[ch + 0], o.x);
            atomicAdd(&pacc[ch + 1], o.y);
            atomicAdd(&pacc[ch + 2], o.z);
            atomicAdd(&pacc[ch + 3], o.w);
        }
        __syncthreads();
        if (tid < 128 && g0 >= 0) atomicAdd(&g_pool[g0 * 128 + tid], pacc[tid]);
    } else {
        if (valid) {
            atomicAdd(&g_pool[gid * 128 + ch + 0], o.x);
            atomicAdd(&g_pool[gid * 128 + ch + 1], o.y);
            atomicAdd(&g_pool[gid * 128 + ch + 2], o.z);
            atomicAdd(&g_pool[gid * 128 + ch + 3], o.w);
        }
        __syncthreads();
    }
}

// ---------------- classifier + sigmoid ----------------
__global__ void k_final(const float* __restrict__ Wc, const float* __restrict__ bc,
                        float* __restrict__ out) {
    int g = blockIdx.x;
    int c = threadIdx.x;
    float s = bc[c];
    #pragma unroll 4
    for (int k = 0; k < 128; k++)
        s = fmaf(g_pool[g * 128 + k], Wc[k * 64 + c], s);
    out[g * 64 + c] = 1.f / (1.f + expf(-s));
}

// ---------------- launch ----------------
extern "C" void kernel_launch(void* const* d_in, const int* in_sizes, int n_in,
                              void* d_out, int out_size) {
    const float* x     = (const float*)d_in[0];
    const void*  ei    = d_in[1];
    const float* ew    = (const float*)d_in[2];
    const void*  batch = d_in[3];
    const float* W1    = (const float*)d_in[4];
    const float* b1    = (const float*)d_in[5];
    const float* W2    = (const float*)d_in[6];
    const float* b2    = (const float*)d_in[7];
    const float* Wc    = (const float*)d_in[8];
    const float* bc    = (const float*)d_in[9];
    float* out = (float*)d_out;

    cudaFuncSetAttribute(k_gemm_tc, cudaFuncAttributeMaxDynamicSharedMemorySize, SME_TOTAL);

    __half* d_y; cudaGetSymbolAddress((void**)&d_y, g_y16);
    float* d_h;  cudaGetSymbolAddress((void**)&d_h,  g_h);
    __nv_bfloat16 *d_w1hi, *d_w1lo, *d_w2hi, *d_w2lo;
    cudaGetSymbolAddress((void**)&d_w1hi, g_w1hi);
    cudaGetSymbolAddress((void**)&d_w1lo, g_w1lo);
    cudaGetSymbolAddress((void**)&d_w2hi, g_w2hi);
    cudaGetSymbolAddress((void**)&d_w2lo, g_w2lo);

    const int TB = 256;
    const int egrid = (N_EDGES + TB - 1) / TB;
    const int ngrid = (N_NODES + TB - 1) / TB;
    const int nb_scan = (N_NODES + 1023) / 1024;
    const int wgrid = (N_NODES * 32 + TB - 1) / TB;   // warp per node

    // dtype probe + weight split + init + CSR build (R5-proven structure)
    k_detect<<<1, 32>>>((const int*)ei);
    k_wsplit<<<64, 256>>>(W1, d_w1hi, d_w1lo);
    k_wsplit<<<64, 256>>>(W2, d_w2hi, d_w2lo);
    k_zero<<<ngrid, TB>>>();
    k_pass1<<<egrid, TB>>>(ei, ew);
    k_dinv<<<ngrid, TB>>>();
    k_scan1<<<nb_scan, 1024>>>(N_NODES);
    k_scan2<<<1, 32>>>(nb_scan);
    k_scan3<<<ngrid, TB>>>(N_NODES);
    k_cursor<<<ngrid, TB>>>(N_NODES);
    k_fill<<<egrid, TB>>>(ei, ew);

    const int mma_grid = (N_NODES + 127) / 128;

    // layer 1
    k_gemm_tc<<<mma_grid, 256, SME_TOTAL>>>(x, d_w1hi, d_w1lo, d_y, N_NODES);
    k_agg<<<wgrid, TB>>>(d_y, b1, d_h);
    // layer 2 (aggregation fused with pooling)
    k_gemm_tc<<<mma_grid, 256, SME_TOTAL>>>(d_h, d_w2hi, d_w2lo, d_y, N_NODES);
    k_agg_pool<<<(N_NODES + 7) / 8, 256>>>(d_y, b2, batch);

    // classifier
    k_final<<<N_GRAPHS, OUT_CH>>>(Wc, bc, out);

    (void)in_sizes; (void)n_in; (void)out_size;
}

// round 9
// speedup vs baseline: 1.7374x; 1.0061x over previous
#include <cuda_runtime.h>
#include <cuda_bf16.h>
#include <cuda_fp16.h>
#include <math.h>
#include <stdint.h>

// Problem constants (match reference)
#define N_NODES  100000
#define N_EDGES  3200000
#define IN_CH    128
#define HID_CH   128
#define OUT_CH   64
#define N_GRAPHS 128

// ---------------- scratch (device globals; no allocation allowed) ----------------
__device__ float g_deg[N_NODES];
__device__ float g_dinv[N_NODES];
__device__ int   g_cnt[N_NODES];
__device__ int   g_ptr[N_NODES + 1];
__device__ int   g_cursor[N_NODES];
__device__ int   g_bsum[128];
__device__ int   g_boff[128];
__device__ int2  g_csr[N_EDGES];                 // {src, __float_as_int(raw edge weight)}
__device__ __half g_y16[N_NODES * HID_CH];       // dinv-prescaled GEMM output (gather operand)
__device__ __half g_h16[N_NODES * HID_CH];       // post-aggregation activations (fp16)
__device__ float g_pool[N_GRAPHS * HID_CH];
__device__ int   g_is64;                         // 1 if index tensors are int64
// bf16-split transposed weights: wt[n*128+k] = W[k*128+n]
__device__ __nv_bfloat16 g_w1hi[HID_CH * IN_CH];
__device__ __nv_bfloat16 g_w1lo[HID_CH * IN_CH];
__device__ __nv_bfloat16 g_w2hi[HID_CH * HID_CH];
__device__ __nv_bfloat16 g_w2lo[HID_CH * HID_CH];

__device__ __forceinline__ uint32_t smem_u32(const void* p) {
    uint32_t a;
    asm("{ .reg .u64 t; cvta.to.shared.u64 t, %1; cvt.u32.u64 %0, t; }" : "=r"(a) : "l"(p));
    return a;
}

// ---------------- index accessor (int32 or int64) ----------------
__device__ __forceinline__ int load_idx(const void* p, long long i, int is64) {
    if (is64) return (int)((const long long*)p)[i];
    return ((const int*)p)[i];
}

__global__ void k_detect(const int* p) {
    if (threadIdx.x == 0 && blockIdx.x == 0) {
        int nz = 0;
        for (int i = 0; i < 64; i++) nz |= p[2 * i + 1];
        g_is64 = (nz == 0) ? 1 : 0;
    }
}

// ---------------- weight transpose + bf16 split ----------------
__global__ void k_wsplit(const float* __restrict__ W, __nv_bfloat16* __restrict__ hi,
                         __nv_bfloat16* __restrict__ lo) {
    int i = blockIdx.x * blockDim.x + threadIdx.x;   // i = k*128 + n
    if (i >= 128 * 128) return;
    int k = i >> 7, n = i & 127;
    float w = W[i];
    __nv_bfloat16 h = __float2bfloat16_rn(w);
    __nv_bfloat16 l = __float2bfloat16_rn(w - __bfloat162float(h));
    hi[n * 128 + k] = h;
    lo[n * 128 + k] = l;
}

// ---------------- init ----------------
__global__ void k_zero() {
    int i = blockIdx.x * blockDim.x + threadIdx.x;
    if (i < N_NODES) { g_deg[i] = 0.f; g_cnt[i] = 0; }
    if (i < N_GRAPHS * HID_CH) g_pool[i] = 0.f;
}

// ---------------- pass 1: degree + per-target edge counts ----------------
__global__ void k_pass1(const void* __restrict__ ei, const float* __restrict__ w) {
    int e = blockIdx.x * blockDim.x + threadIdx.x;
    if (e >= N_EDGES) return;
    int is64 = g_is64;
    int c = load_idx(ei, (long long)N_EDGES + e, is64);
    atomicAdd(&g_deg[c], w[e]);
    atomicAdd(&g_cnt[c], 1);
}

__global__ void k_dinv() {
    int i = blockIdx.x * blockDim.x + threadIdx.x;
    if (i >= N_NODES) return;
    g_dinv[i] = rsqrtf(g_deg[i] + 1.0f);
}

// ---------------- exclusive scan of counts -> g_ptr ----------------
__global__ void k_scan1(int n) {
    __shared__ int sm[1024];
    int i = blockIdx.x * 1024 + threadIdx.x;
    int v = (i < n) ? g_cnt[i] : 0;
    sm[threadIdx.x] = v;
    __syncthreads();
    for (int off = 1; off < 1024; off <<= 1) {
        int t = (threadIdx.x >= off) ? sm[threadIdx.x - off] : 0;
        __syncthreads();
        sm[threadIdx.x] += t;
        __syncthreads();
    }
    if (i < n) g_ptr[i + 1] = sm[threadIdx.x];
    if (threadIdx.x == 1023) g_bsum[blockIdx.x] = sm[1023];
}

__global__ void k_scan2(int nb) {
    if (threadIdx.x == 0 && blockIdx.x == 0) {
        int acc = 0;
        for (int b = 0; b < nb; b++) { int t = g_bsum[b]; g_boff[b] = acc; acc += t; }
    }
}

__global__ void k_scan3(int n) {
    int i = blockIdx.x * blockDim.x + threadIdx.x;
    if (i == 0) g_ptr[0] = 0;
    if (i < n) g_ptr[i + 1] += g_boff[i >> 10];
}

__global__ void k_cursor(int n) {
    int i = blockIdx.x * blockDim.x + threadIdx.x;
    if (i < n) g_cursor[i] = g_ptr[i];
}

// ---------------- pass 2: fill CSR with (src, raw weight) — no random reads ----------------
__global__ void k_fill(const void* __restrict__ ei, const float* __restrict__ w) {
    int e = blockIdx.x * blockDim.x + threadIdx.x;
    if (e >= N_EDGES) return;
    int is64 = g_is64;
    int r = load_idx(ei, e, is64);
    int c = load_idx(ei, (long long)N_EDGES + e, is64);
    int p = atomicAdd(&g_cursor[c], 1);
    g_csr[p] = make_int2(r, __float_as_int(w[e]));
}

// ---------------- mma.sync GEMM: Y[M,128] = fp16(dinv .* (A[M,128] @ W)) (3x bf16 split) ----------------
// Block = 128x128, 256 threads (8 warps). Warp w: rows w*16..w*16+15, all 128 cols.
// smem: Ah, Al, Bs each [128][PADK] bf16 -> 104,448 B total -> 2 blocks/SM.
// Pass order: (AhiBhi, AloBhi) with Bs=Whi, then reload Bs=Wlo, then AhiBlo.
// Templated on A dtype: fp32 (layer 1 input x) or fp16 (layer 2 activations h).
#define PADK 136
#define SME_TOTAL (3 * 128 * PADK * 2)

template <bool AHALF>
__global__ __launch_bounds__(256, 2) void k_gemm_tc(const void* __restrict__ Araw,
                                                    const __nv_bfloat16* __restrict__ wt_hi,
                                                    const __nv_bfloat16* __restrict__ wt_lo,
                                                    __half* __restrict__ Y, int M) {
    extern __shared__ char smem_raw[];
    __nv_bfloat16* Ah = (__nv_bfloat16*)smem_raw;
    __nv_bfloat16* Al = Ah + 128 * PADK;
    __nv_bfloat16* Bs = Al + 128 * PADK;
    int tid = threadIdx.x;
    int wid = tid >> 5, lane = tid & 31;
    int row0 = blockIdx.x * 128;

    // Load A [128x128] -> hi/lo bf16 split
    for (int g = tid; g < 128 * 32; g += 256) {
        int r = g >> 5, c4 = (g & 31) * 4;
        int gr = row0 + r;
        float4 v = make_float4(0.f, 0.f, 0.f, 0.f);
        if (gr < M) {
            if (AHALF) {
                const __half* Ap = (const __half*)Araw;
                uint2 raw = *(const uint2*)(Ap + (size_t)gr * 128 + c4);
                float2 f01 = __half22float2(*(__half2*)&raw.x);
                float2 f23 = __half22float2(*(__half2*)&raw.y);
                v = make_float4(f01.x, f01.y, f23.x, f23.y);
            } else {
                v = ((const float4*)((const float*)Araw + (size_t)gr * 128))[c4 >> 2];
            }
        }
        __nv_bfloat16 h0 = __float2bfloat16_rn(v.x), h1 = __float2bfloat16_rn(v.y);
        __nv_bfloat16 h2 = __float2bfloat16_rn(v.z), h3 = __float2bfloat16_rn(v.w);
        __nv_bfloat16* ah = Ah + r * PADK + c4;
        __nv_bfloat16* al = Al + r * PADK + c4;
        ah[0] = h0; ah[1] = h1; ah[2] = h2; ah[3] = h3;
        al[0] = __float2bfloat16_rn(v.x - __bfloat162float(h0));
        al[1] = __float2bfloat16_rn(v.y - __bfloat162float(h1));
        al[2] = __float2bfloat16_rn(v.z - __bfloat162float(h2));
        al[3] = __float2bfloat16_rn(v.w - __bfloat162float(h3));
    }
    // Load B = W_hi (pre-split transposed weights)
    for (int g = tid; g < 128 * 16; g += 256) {
        int r = g >> 4, c8 = (g & 15) * 8;
        *(float4*)(Bs + r * PADK + c8) = *(const float4*)(wt_hi + r * 128 + c8);
    }
    __syncthreads();

    float acc[16][4];
    #pragma unroll
    for (int nt = 0; nt < 16; nt++)
        #pragma unroll
        for (int j = 0; j < 4; j++) acc[nt][j] = 0.f;

    int rowA = wid * 16;
    int a_r = rowA + (lane & 15);
    int a_c = (lane >> 4) * 8;
    int b_r = (lane & 7);
    int b_c = ((lane >> 3) & 1) * 8;

    uint32_t abase_h = smem_u32(Ah + a_r * PADK + a_c);
    uint32_t abase_l = smem_u32(Al + a_r * PADK + a_c);
    uint32_t bbase   = smem_u32(Bs + b_r * PADK + b_c);

    // passes with Bs = W_hi: AhiBhi then AloBhi
    #pragma unroll
    for (int pass = 0; pass < 2; pass++) {
        uint32_t abase = (pass == 0) ? abase_h : abase_l;
        #pragma unroll
        for (int kc = 0; kc < 8; kc++) {
            uint32_t a0, a1, a2, a3;
            asm volatile("ldmatrix.sync.aligned.m8n8.x4.shared.b16 {%0,%1,%2,%3}, [%4];"
                         : "=r"(a0), "=r"(a1), "=r"(a2), "=r"(a3)
                         : "r"(abase + kc * 32));
            #pragma unroll
            for (int nt = 0; nt < 16; nt++) {
                uint32_t b0, b1;
                asm volatile("ldmatrix.sync.aligned.m8n8.x2.shared.b16 {%0,%1}, [%2];"
                             : "=r"(b0), "=r"(b1)
                             : "r"(bbase + (uint32_t)(nt * 8 * PADK * 2) + kc * 32));
                asm volatile("mma.sync.aligned.m16n8k16.row.col.f32.bf16.bf16.f32 "
                             "{%0,%1,%2,%3}, {%4,%5,%6,%7}, {%8,%9}, {%0,%1,%2,%3};"
                             : "+f"(acc[nt][0]), "+f"(acc[nt][1]), "+f"(acc[nt][2]), "+f"(acc[nt][3])
                             : "r"(a0), "r"(a1), "r"(a2), "r"(a3), "r"(b0), "r"(b1));
            }
        }
    }

    // swap B to W_lo
    __syncthreads();
    for (int g = tid; g < 128 * 16; g += 256) {
        int r = g >> 4, c8 = (g & 15) * 8;
        *(float4*)(Bs + r * PADK + c8) = *(const float4*)(wt_lo + r * 128 + c8);
    }
    __syncthreads();

    // pass AhiBlo
    #pragma unroll
    for (int kc = 0; kc < 8; kc++) {
        uint32_t a0, a1, a2, a3;
        asm volatile("ldmatrix.sync.aligned.m8n8.x4.shared.b16 {%0,%1,%2,%3}, [%4];"
                     : "=r"(a0), "=r"(a1), "=r"(a2), "=r"(a3)
                     : "r"(abase_h + kc * 32));
        #pragma unroll
        for (int nt = 0; nt < 16; nt++) {
            uint32_t b0, b1;
            asm volatile("ldmatrix.sync.aligned.m8n8.x2.shared.b16 {%0,%1}, [%2];"
                         : "=r"(b0), "=r"(b1)
                         : "r"(bbase + (uint32_t)(nt * 8 * PADK * 2) + kc * 32));
            asm volatile("mma.sync.aligned.m16n8k16.row.col.f32.bf16.bf16.f32 "
                         "{%0,%1,%2,%3}, {%4,%5,%6,%7}, {%8,%9}, {%0,%1,%2,%3};"
                         : "+f"(acc[nt][0]), "+f"(acc[nt][1]), "+f"(acc[nt][2]), "+f"(acc[nt][3])
                         : "r"(a0), "r"(a1), "r"(a2), "r"(a3), "r"(b0), "r"(b1));
        }
    }

    // Epilogue: scale by dinv[row], pack to fp16.
    int er0 = row0 + rowA + (lane >> 2);
    int er1 = er0 + 8;
    int ec = (lane & 3) * 2;
    float d0 = (er0 < M) ? g_dinv[er0] : 0.f;
    float d1 = (er1 < M) ? g_dinv[er1] : 0.f;
    #pragma unroll
    for (int nt = 0; nt < 16; nt++) {
        if (er0 < M)
            *(__half2*)(Y + (size_t)er0 * 128 + nt * 8 + ec) =
                __floats2half2_rn(acc[nt][0] * d0, acc[nt][1] * d0);
        if (er1 < M)
            *(__half2*)(Y + (size_t)er1 * 128 + nt * 8 + ec) =
                __floats2half2_rn(acc[nt][2] * d1, acc[nt][3] * d1);
    }
}

// ---------------- core aggregation for one node (warp-collective), returns float4 ----------------
__device__ __forceinline__ float4 agg_node(const __half* __restrict__ y, int node, int lane, int ch) {
    int beg = g_ptr[node], end = g_ptr[node + 1];
    float a0 = 0.f, a1 = 0.f, a2 = 0.f, a3 = 0.f;
    for (int e = beg; e < end; e += 32) {
        int n = min(32, end - e);
        int2 ed = (lane < n) ? g_csr[e + lane] : make_int2(0, 0);
        int j = 0;
        for (; j + 1 < n; j += 2) {
            int   s0 = __shfl_sync(0xffffffffu, ed.x, j);
            float w0 = __int_as_float(__shfl_sync(0xffffffffu, ed.y, j));
            int   s1 = __shfl_sync(0xffffffffu, ed.x, j + 1);
            float w1 = __int_as_float(__shfl_sync(0xffffffffu, ed.y, j + 1));
            float2 r0 = *(const float2*)(y + (size_t)s0 * 128 + ch);
            float2 r1 = *(const float2*)(y + (size_t)s1 * 128 + ch);
            float2 p0 = __half22float2(*(__half2*)&r0.x);
            float2 p1 = __half22float2(*(__half2*)&r0.y);
            float2 q0 = __half22float2(*(__half2*)&r1.x);
            float2 q1 = __half22float2(*(__half2*)&r1.y);
            a0 = fmaf(p0.x, w0, a0); a1 = fmaf(p0.y, w0, a1);
            a2 = fmaf(p1.x, w0, a2); a3 = fmaf(p1.y, w0, a3);
            a0 = fmaf(q0.x, w1, a0); a1 = fmaf(q0.y, w1, a1);
            a2 = fmaf(q1.x, w1, a2); a3 = fmaf(q1.y, w1, a3);
        }
        if (j < n) {
            int   s0 = __shfl_sync(0xffffffffu, ed.x, j);
            float w0 = __int_as_float(__shfl_sync(0xffffffffu, ed.y, j));
            float2 r0 = *(const float2*)(y + (size_t)s0 * 128 + ch);
            float2 p0 = __half22float2(*(__half2*)&r0.x);
            float2 p1 = __half22float2(*(__half2*)&r0.y);
            a0 = fmaf(p0.x, w0, a0); a1 = fmaf(p0.y, w0, a1);
            a2 = fmaf(p1.x, w0, a2); a3 = fmaf(p1.y, w0, a3);
        }
    }
    // self loop: +y_i (weight 1 in prescaled space)
    float2 r0 = *(const float2*)(y + (size_t)node * 128 + ch);
    float2 p0 = __half22float2(*(__half2*)&r0.x);
    float2 p1 = __half22float2(*(__half2*)&r0.y);
    a0 += p0.x; a1 += p0.y; a2 += p1.x; a3 += p1.y;
    return make_float4(a0, a1, a2, a3);
}

// ---------------- aggregation layer 1: write fp16 h ----------------
__global__ void k_agg(const __half* __restrict__ y, const float* __restrict__ bias,
                      __half* __restrict__ out) {
    int node = (blockIdx.x * blockDim.x + threadIdx.x) >> 5;
    if (node >= N_NODES) return;
    int lane = threadIdx.x & 31;
    int ch = lane * 4;
    float4 a = agg_node(y, node, lane, ch);
    float di = g_dinv[node];
    float4 b = *(const float4*)(bias + ch);
    float o0 = fmaxf(fmaf(di, a.x, b.x), 0.f);
    float o1 = fmaxf(fmaf(di, a.y, b.y), 0.f);
    float o2 = fmaxf(fmaf(di, a.z, b.z), 0.f);
    float o3 = fmaxf(fmaf(di, a.w, b.w), 0.f);
    __half2 h01 = __floats2half2_rn(o0, o1);
    __half2 h23 = __floats2half2_rn(o2, o3);
    uint2 packed = make_uint2(*(uint32_t*)&h01, *(uint32_t*)&h23);
    *(uint2*)(out + (size_t)node * 128 + ch) = packed;
}

// ---------------- aggregation layer 2 fused with pooling ----------------
// Block = 8 warps = 8 consecutive nodes. Accumulate relu'd rows into per-block
// smem when all nodes share a graph (the common case), else direct atomics.
__global__ void k_agg_pool(const __half* __restrict__ y, const float* __restrict__ bias,
                           const void* __restrict__ batch) {
    __shared__ float pacc[128];
    __shared__ int   sg[8];
    int tid = threadIdx.x;
    int wid = tid >> 5, lane = tid & 31;
    int node = blockIdx.x * 8 + wid;
    bool valid = node < N_NODES;
    int ch = lane * 4;

    int gid = -1;
    if (valid) gid = load_idx(batch, node, g_is64);
    if (lane == 0) sg[wid] = gid;
    if (tid < 128) pacc[tid] = 0.f;

    float4 o = make_float4(0.f, 0.f, 0.f, 0.f);
    if (valid) {
        float4 a = agg_node(y, node, lane, ch);
        float di = g_dinv[node];
        float4 b = *(const float4*)(bias + ch);
        o.x = fmaxf(fmaf(di, a.x, b.x), 0.f);
        o.y = fmaxf(fmaf(di, a.y, b.y), 0.f);
        o.z = fmaxf(fmaf(di, a.z, b.z), 0.f);
        o.w = fmaxf(fmaf(di, a.w, b.w), 0.f);
    }
    __syncthreads();

    int g0 = sg[0];
    bool uni = true;
    #pragma unroll
    for (int w = 1; w < 8; w++) uni = uni && (sg[w] == g0 || sg[w] < 0);

    if (uni) {
        if (valid) {
            atomicAdd(&pacc[ch + 0], o.x);
            atomicAdd(&pacc[ch + 1], o.y);
            atomicAdd(&pacc[ch + 2], o.z);
            atomicAdd(&pacc[ch + 3], o.w);
        }
        __syncthreads();
        if (tid < 128 && g0 >= 0) atomicAdd(&g_pool[g0 * 128 + tid], pacc[tid]);
    } else {
        if (valid) {
            atomicAdd(&g_pool[gid * 128 + ch + 0], o.x);
            atomicAdd(&g_pool[gid * 128 + ch + 1], o.y);
            atomicAdd(&g_pool[gid * 128 + ch + 2], o.z);
            atomicAdd(&g_pool[gid * 128 + ch + 3], o.w);
        }
        __syncthreads();
    }
}

// ---------------- classifier + sigmoid ----------------
__global__ void k_final(const float* __restrict__ Wc, const float* __restrict__ bc,
                        float* __restrict__ out) {
    int g = blockIdx.x;
    int c = threadIdx.x;
    float s = bc[c];
    #pragma unroll 4
    for (int k = 0; k < 128; k++)
        s = fmaf(g_pool[g * 128 + k], Wc[k * 64 + c], s);
    out[g * 64 + c] = 1.f / (1.f + expf(-s));
}

// ---------------- launch ----------------
extern "C" void kernel_launch(void* const* d_in, const int* in_sizes, int n_in,
                              void* d_out, int out_size) {
    const float* x     = (const float*)d_in[0];
    const void*  ei    = d_in[1];
    const float* ew    = (const float*)d_in[2];
    const void*  batch = d_in[3];
    const float* W1    = (const float*)d_in[4];
    const float* b1    = (const float*)d_in[5];
    const float* W2    = (const float*)d_in[6];
    const float* b2    = (const float*)d_in[7];
    const float* Wc    = (const float*)d_in[8];
    const float* bc    = (const float*)d_in[9];
    float* out = (float*)d_out;

    cudaFuncSetAttribute(k_gemm_tc<false>, cudaFuncAttributeMaxDynamicSharedMemorySize, SME_TOTAL);
    cudaFuncSetAttribute(k_gemm_tc<true>,  cudaFuncAttributeMaxDynamicSharedMemorySize, SME_TOTAL);

    __half* d_y; cudaGetSymbolAddress((void**)&d_y, g_y16);
    __half* d_h; cudaGetSymbolAddress((void**)&d_h, g_h16);
    __nv_bfloat16 *d_w1hi, *d_w1lo, *d_w2hi, *d_w2lo;
    cudaGetSymbolAddress((void**)&d_w1hi, g_w1hi);
    cudaGetSymbolAddress((void**)&d_w1lo, g_w1lo);
    cudaGetSymbolAddress((void**)&d_w2hi, g_w2hi);
    cudaGetSymbolAddress((void**)&d_w2lo, g_w2lo);

    const int TB = 256;
    const int egrid = (N_EDGES + TB - 1) / TB;
    const int ngrid = (N_NODES + TB - 1) / TB;
    const int nb_scan = (N_NODES + 1023) / 1024;
    const int wgrid = (N_NODES * 32 + TB - 1) / TB;   // warp per node

    // dtype probe + weight split + init + CSR build (R8-proven structure)
    k_detect<<<1, 32>>>((const int*)ei);
    k_wsplit<<<64, 256>>>(W1, d_w1hi, d_w1lo);
    k_wsplit<<<64, 256>>>(W2, d_w2hi, d_w2lo);
    k_zero<<<ngrid, TB>>>();
    k_pass1<<<egrid, TB>>>(ei, ew);
    k_dinv<<<ngrid, TB>>>();
    k_scan1<<<nb_scan, 1024>>>(N_NODES);
    k_scan2<<<1, 32>>>(nb_scan);
    k_scan3<<<ngrid, TB>>>(N_NODES);
    k_cursor<<<ngrid, TB>>>(N_NODES);
    k_fill<<<egrid, TB>>>(ei, ew);

    const int mma_grid = (N_NODES + 127) / 128;

    // layer 1 (A = fp32 x)
    k_gemm_tc<false><<<mma_grid, 256, SME_TOTAL>>>(x, d_w1hi, d_w1lo, d_y, N_NODES);
    k_agg<<<wgrid, TB>>>(d_y, b1, d_h);
    // layer 2 (A = fp16 h; aggregation fused with pooling)
    k_gemm_tc<true><<<mma_grid, 256, SME_TOTAL>>>(d_h, d_w2hi, d_w2lo, d_y, N_NODES);
    k_agg_pool<<<(N_NODES + 7) / 8, 256>>>(d_y, b2, batch);

    // classifier
    k_final<<<N_GRAPHS, OUT_CH>>>(Wc, bc, out);

    (void)in_sizes; (void)n_in; (void)out_size;
}